// round 6
// baseline (speedup 1.0000x reference)
#include <cuda_runtime.h>
#include <cuda_bf16.h>

// Fixed problem shape
#define Nn 128
#define Tt 1024
#define Cc 256
#define Ll 128
#define Ss 257            // 2*L+1
#define NEGV    (-1e30f)
#define INV_LN2 1.4426950408889634f
#define LN2     0.6931471805599453f
#define MAGIC   (-1e38f)  // "lse not ready" sentinel (real lse2 ~ +8.7)
#define RSTG 16           // preds-row smem ring depth

__device__ float g_losses[Nn];

// ---------------------------------------------------------------------------
// helpers
// ---------------------------------------------------------------------------
__device__ __forceinline__ float ex2f_(float x) {
    float y; asm("ex2.approx.ftz.f32 %0, %1;" : "=f"(y) : "f"(x)); return y;
}
__device__ __forceinline__ float lg2f_(float x) {
    float y; asm("lg2.approx.ftz.f32 %0, %1;" : "=f"(y) : "f"(x)); return y;
}
__device__ __forceinline__ float ld_acq_f(const float* p) {
    unsigned a = (unsigned)__cvta_generic_to_shared((const void*)p);
    int v; asm volatile("ld.acquire.cta.shared.b32 %0, [%1];"
                        : "=r"(v) : "r"(a) : "memory");
    return __int_as_float(v);
}
__device__ __forceinline__ void st_rel_f(float* p, float v) {
    unsigned a = (unsigned)__cvta_generic_to_shared((void*)p);
    asm volatile("st.release.cta.shared.b32 [%0], %1;"
                 :: "r"(a), "r"(__float_as_int(v)) : "memory");
}
__device__ __forceinline__ int ld_acq_i(const int* p) {
    unsigned a = (unsigned)__cvta_generic_to_shared((const void*)p);
    int v; asm volatile("ld.acquire.cta.shared.b32 %0, [%1];"
                        : "=r"(v) : "r"(a) : "memory");
    return v;
}
__device__ __forceinline__ void st_rel_i(int* p, int v) {
    unsigned a = (unsigned)__cvta_generic_to_shared((void*)p);
    asm volatile("st.release.cta.shared.b32 [%0], %1;"
                 :: "r"(a), "r"(v) : "memory");
}
__device__ __forceinline__ void bar_rec() {   // named barrier: recursion warps only
    asm volatile("bar.sync 1, 128;" ::: "memory");
}

// ---------------------------------------------------------------------------
// Fused CTC kernel: one block per batch element n. 256 threads.
//   warps 0-3 (tid   0..127): alpha recursion; thread i owns s=2i, 2i+1,
//                             thread 0 additionally owns s=256.
//                             synced by bar.sync 1,128.
//   warps 4-7 (tid 128..255): free-running producers — stream preds rows
//                             (2-deep prefetch) into smem ring + per-row
//                             base-2 lse; publish via s_lse[t] value-is-flag
//                             (__syncwarp + st.release — NO threadfence).
// ---------------------------------------------------------------------------
__global__ void __launch_bounds__(256) ctc_fused(const float* __restrict__ preds,
                                                 const int*   __restrict__ targets) {
    __shared__ int   s_tg[Ll];
    __shared__ float s_lse[Tt];                       // 4 KB, value-is-flag, BASE-2
    __shared__ __align__(16) float rows[RSTG][Cc];    // 16 KB ring
    __shared__ __align__(16) float As[2][264];        // alpha, k = s+2
    __shared__ int   s_tdone;

    const int n   = blockIdx.x;
    const int tid = threadIdx.x;
    const size_t base = (size_t)n * Tt * Cc;

    int tgv = (tid < Ll) ? targets[n * Ll + tid] : 0;
    if (tid < Ll) s_tg[tid] = tgv;
    for (int k = tid; k < Tt; k += 256) s_lse[k] = MAGIC;
    if (tid == 0) s_tdone = -1;
    if (tid < 2) { As[0][tid] = NEGV; As[1][tid] = NEGV; }
    const int tl = __syncthreads_count(tgv != 0);     // the only block-wide bar

    if (tid >= 128) {
        // ================= producers =================
        const int w    = (tid >> 5) - 4;     // 0..3: rows w, w+4, w+8, ...
        const int lane = tid & 31;
        const float4* p4 = (const float4*)(preds + base);

        // 2-deep prefetch
        float4 f0 = __ldg(p4 + (size_t)w * 64 + lane);
        float4 f1 = __ldg(p4 + (size_t)w * 64 + lane + 32);
        float4 g0 = __ldg(p4 + (size_t)(w + 4) * 64 + lane);
        float4 g1 = __ldg(p4 + (size_t)(w + 4) * 64 + lane + 32);

        for (int t = w; t < Tt; t += 4) {
            int t2 = t + 8;
            float4 h0, h1;
            if (t2 < Tt) {
                h0 = __ldg(p4 + (size_t)t2 * 64 + lane);
                h1 = __ldg(p4 + (size_t)t2 * 64 + lane + 32);
            }
            // backpressure: slot (t & 15) reusable once recursion passed t-16
            if (t >= RSTG) { while (ld_acq_i(&s_tdone) + RSTG < t) { } }

            // stage row into ring
            float4* dst = (float4*)rows[t & (RSTG - 1)];
            dst[lane]      = f0;
            dst[lane + 32] = f1;
            __syncwarp();      // order all lanes' row stores before lane0's flag

            // row logsumexp in BASE-2 (no max: logits are O(1))
            float S = ex2f_(f0.x * INV_LN2) + ex2f_(f0.y * INV_LN2)
                    + ex2f_(f0.z * INV_LN2) + ex2f_(f0.w * INV_LN2)
                    + ex2f_(f1.x * INV_LN2) + ex2f_(f1.y * INV_LN2)
                    + ex2f_(f1.z * INV_LN2) + ex2f_(f1.w * INV_LN2);
#pragma unroll
            for (int o = 16; o; o >>= 1) S += __shfl_xor_sync(0xffffffffu, S, o);
            if (lane == 0) st_rel_f(&s_lse[t], lg2f_(S));

            f0 = g0; f1 = g1; g0 = h0; g1 = h1;
        }
        return;
    }

    // ================= recursion =================
    const int i = tid;                         // owns s = 2i, 2i+1 (+ s=256 if i==0)

    int myc = s_tg[i];                         // class of odd pos s=2i+1
    int pv2 = (i >= 1) ? s_tg[i - 1] : 0;
    const bool sk = (myc != 0) && (myc != pv2);

    // t = 0 init  (alpha in base-2; s_lse is base-2)
    float lse0 = ld_acq_f(&s_lse[0]);
    while (lse0 == MAGIC) lse0 = ld_acq_f(&s_lse[0]);
    {
        float pB = __ldg(preds + base + 0);
        float pL = __ldg(preds + base + s_tg[0]);
        float rE = (i == 0) ? (pB * INV_LN2 - lse0) : NEGV;   // s=0
        float rO = (i == 0) ? (pL * INV_LN2 - lse0) : NEGV;   // s=1
        ((float2*)&As[0][2])[i] = make_float2(rE, rO);
        if (i == 0) { As[0][258] = NEGV; As[1][258] = NEGV; } // s=256
    }
    bar_rec();

    // prefetch step t=1 emission log-probs (base-2)
    float lp2B, lp2L;
    {
        float l1 = ld_acq_f(&s_lse[1]);
        while (l1 == MAGIC) l1 = ld_acq_f(&s_lse[1]);
        lp2B = rows[1][0]   * INV_LN2 - l1;
        lp2L = rows[1][myc] * INV_LN2 - l1;
    }

    for (int t = 1; t < Tt; ++t) {
        const int p = (t - 1) & 1, c = t & 1;
        {
            const float2* src = (const float2*)&As[p][0];
            float2 v0 = src[i];        // s = 2i-2, 2i-1
            float2 v1 = src[i + 1];    // s = 2i,   2i+1
            float aEm1 = v0.y, aE0 = v1.x, aO0 = v1.y;

            // shared max for both positions
            float m  = fmaxf(fmaxf(aE0, aEm1), aO0);
            float e0 = ex2f_(aE0  - m);
            float e1 = ex2f_(aEm1 - m);
            float e2 = ex2f_(aO0  - m);

            // even pos s=2i (blank): stay + step
            float rE = m + lg2f_(e0 + e1) + lp2B;
            // odd pos s=2i+1: stay + step + (skip)
            float rO = m + lg2f_(e2 + e0 + (sk ? e1 : 0.0f)) + lp2L;

            // clamp: restores NEGV semantics for -inf/NaN (all-NEGV neighborhoods)
            rE = fmaxf(rE, NEGV);
            rO = fmaxf(rO, NEGV);
            ((float2*)&As[c][2])[i] = make_float2(rE, rO);

            if (i == 0) {              // s=256 (blank): stay + step
                float a255 = As[p][257];
                float a256 = As[p][258];
                float m2 = fmaxf(a255, a256);
                float r  = m2 + lg2f_(ex2f_(a255 - m2) + ex2f_(a256 - m2)) + lp2B;
                As[c][258] = fmaxf(r, NEGV);
            }
        }
        bar_rec();
        if (tid == 0) st_rel_i(&s_tdone, t);

        // prefetch step t+1 (off next iteration's dependent chain)
        int tn = (t + 1 < Tt) ? (t + 1) : (Tt - 1);
        float lse = ld_acq_f(&s_lse[tn]);
        while (lse == MAGIC) lse = ld_acq_f(&s_lse[tn]);
        lp2B = rows[tn & (RSTG - 1)][0]   * INV_LN2 - lse;
        lp2L = rows[tn & (RSTG - 1)][myc] * INV_LN2 - lse;
    }

    if (tid == 0) {
        const int last = (Tt - 1) & 1;
        float f1v = As[last][2 * tl + 2];                        // s = 2*tl
        float f2v = (tl > 0) ? As[last][2 * tl + 1]              // s = 2*tl-1
                             : As[last][258];                    // wrap: s = 256
        float m   = fmaxf(f1v, f2v);
        float fin = (m + lg2f_(ex2f_(f1v - m) + ex2f_(f2v - m))) * LN2;
        float loss = (fin < -1e29f) ? 0.0f : -fin;               // zero_infinity
        int tld = (tl > 0) ? tl : 1;
        g_losses[n] = loss / (float)tld;
    }
}

// ---------------------------------------------------------------------------
// mean over batch -> scalar
// ---------------------------------------------------------------------------
__global__ void __launch_bounds__(128) reduce_kernel(float* __restrict__ out) {
    int tid = threadIdx.x;
    float v = g_losses[tid];
#pragma unroll
    for (int o = 16; o; o >>= 1) v += __shfl_xor_sync(0xffffffffu, v, o);
    __shared__ float sm[4];
    if ((tid & 31) == 0) sm[tid >> 5] = v;
    __syncthreads();
    if (tid == 0) out[0] = (sm[0] + sm[1] + sm[2] + sm[3]) * (1.0f / (float)Nn);
}

// ---------------------------------------------------------------------------
extern "C" void kernel_launch(void* const* d_in, const int* in_sizes, int n_in,
                              void* d_out, int out_size) {
    const float* preds;
    const int*   targets;
    if (in_sizes[0] == Nn * Tt * Cc) {
        preds   = (const float*)d_in[0];
        targets = (const int*)  d_in[1];
    } else {
        preds   = (const float*)d_in[1];
        targets = (const int*)  d_in[0];
    }
    float* out = (float*)d_out;

    ctc_fused   <<<Nn, 256>>>(preds, targets);
    reduce_kernel<<<1, 128>>>(out);
}

// round 8
// speedup vs baseline: 1.7670x; 1.7670x over previous
#include <cuda_runtime.h>
#include <cuda_bf16.h>

// Fixed problem shape
#define Nn 128
#define Tt 1024
#define TM 512            // midpoint: fwd owns t=0..511, bwd owns t=512..1023
#define Cc 256
#define Ll 128
#define NEGV    (-1e30f)
#define INV_LN2 1.4426950408889634f
#define LN2     0.6931471805599453f
#define MAGIC   (-1e38f)
#define RSTG 16

__device__ float g_losses[Nn];

// ---------------------------------------------------------------------------
__device__ __forceinline__ float ex2f_(float x) {
    float y; asm("ex2.approx.ftz.f32 %0, %1;" : "=f"(y) : "f"(x)); return y;
}
__device__ __forceinline__ float lg2f_(float x) {
    float y; asm("lg2.approx.ftz.f32 %0, %1;" : "=f"(y) : "f"(x)); return y;
}
__device__ __forceinline__ float ld_acq_f(const float* p) {
    unsigned a = (unsigned)__cvta_generic_to_shared((const void*)p);
    int v; asm volatile("ld.acquire.cta.shared.b32 %0, [%1];"
                        : "=r"(v) : "r"(a) : "memory");
    return __int_as_float(v);
}
__device__ __forceinline__ void st_rel_f(float* p, float v) {
    unsigned a = (unsigned)__cvta_generic_to_shared((void*)p);
    asm volatile("st.release.cta.shared.b32 [%0], %1;"
                 :: "r"(a), "r"(__float_as_int(v)) : "memory");
}
__device__ __forceinline__ int ld_acq_i(const int* p) {
    unsigned a = (unsigned)__cvta_generic_to_shared((const void*)p);
    int v; asm volatile("ld.acquire.cta.shared.b32 %0, [%1];"
                        : "=r"(v) : "r"(a) : "memory");
    return v;
}
__device__ __forceinline__ void st_rel_i(int* p, int v) {
    unsigned a = (unsigned)__cvta_generic_to_shared((void*)p);
    asm volatile("st.release.cta.shared.b32 [%0], %1;"
                 :: "r"(a), "r"(v) : "memory");
}
#define BARF() asm volatile("bar.sync 1, 128;" ::: "memory")   // fwd recursion
#define BARB() asm volatile("bar.sync 2, 128;" ::: "memory")   // bwd recursion
#define BARC() asm volatile("bar.sync 3, 256;" ::: "memory")   // combine (both)

// ---------------------------------------------------------------------------
// One block per batch element n. 512 threads:
//   tid   0..127 : forward alpha recursion  (t = 0 .. 511)
//   tid 128..255 : backward beta recursion  (t = 1023 .. 512)
//   tid 256..383 : fwd producers (rows 0..511 -> ringF + lse, value-is-flag)
//   tid 384..511 : bwd producers (rows 1023..512 -> ringB + lse)
// Combine at midpoint: loss = logsumexp_s' [ step(alpha_511)(s') + beta~_512(s') ]
// ---------------------------------------------------------------------------
__global__ void __launch_bounds__(512) ctc_fused(const float* __restrict__ preds,
                                                 const int*   __restrict__ targets) {
    __shared__ int   s_tg[Ll];
    __shared__ float s_lse[Tt];                        // base-2, value-is-flag
    __shared__ __align__(16) float ringF[RSTG][Cc];    // 16 KB
    __shared__ __align__(16) float ringB[RSTG][Cc];    // 16 KB
    __shared__ __align__(16) float As[2][264];         // alpha, k = s+2
    __shared__ __align__(16) float Bs[2][264];         // beta,  k = s
    __shared__ int   s_tdF, s_tdB;
    __shared__ float red[8];                           // (M,E) per fwd warp

    const int n   = blockIdx.x;
    const int tid = threadIdx.x;
    const size_t base = (size_t)n * Tt * Cc;

    int tgv = (tid < Ll) ? targets[n * Ll + tid] : 0;
    if (tid < Ll) s_tg[tid] = tgv;
    for (int k = tid; k < Tt; k += 512) s_lse[k] = MAGIC;
    if (tid == 0) { s_tdF = -1; s_tdB = Tt; }
    if (tid < 2)  { As[0][tid] = NEGV; As[1][tid] = NEGV;
                    As[0][258] = NEGV; As[1][258] = NEGV; }
    if (tid >= 8 && tid < 11) { Bs[0][249 + tid] = NEGV; Bs[1][249 + tid] = NEGV; } // k=257..259
    const int tl = __syncthreads_count(tgv != 0);

    const int grp = tid >> 7;

    if (grp >= 2) {
        // ======================= producers =======================
        const int lane = tid & 31;
        const float4* p4 = (const float4*)(preds + base);
        if (grp == 2) {
            // forward: rows w, w+4, ... < 512
            const int w = (tid >> 5) - 8;
            float4 f0 = __ldg(p4 + (size_t)w * 64 + lane);
            float4 f1 = __ldg(p4 + (size_t)w * 64 + lane + 32);
            float4 g0 = __ldg(p4 + (size_t)(w + 4) * 64 + lane);
            float4 g1 = __ldg(p4 + (size_t)(w + 4) * 64 + lane + 32);
            for (int t = w; t < TM; t += 4) {
                int t2 = t + 8;
                float4 h0, h1;
                if (t2 < TM) {
                    h0 = __ldg(p4 + (size_t)t2 * 64 + lane);
                    h1 = __ldg(p4 + (size_t)t2 * 64 + lane + 32);
                }
                if (t >= RSTG) { while (ld_acq_i(&s_tdF) + RSTG < t) { } }
                float4* dst = (float4*)ringF[t & (RSTG - 1)];
                dst[lane] = f0; dst[lane + 32] = f1;
                __syncwarp();
                float S = ex2f_(f0.x * INV_LN2) + ex2f_(f0.y * INV_LN2)
                        + ex2f_(f0.z * INV_LN2) + ex2f_(f0.w * INV_LN2)
                        + ex2f_(f1.x * INV_LN2) + ex2f_(f1.y * INV_LN2)
                        + ex2f_(f1.z * INV_LN2) + ex2f_(f1.w * INV_LN2);
#pragma unroll
                for (int o = 16; o; o >>= 1) S += __shfl_xor_sync(0xffffffffu, S, o);
                if (lane == 0) st_rel_f(&s_lse[t], lg2f_(S));
                f0 = g0; f1 = g1; g0 = h0; g1 = h1;
            }
        } else {
            // backward: rows 1023-w, 1019-w, ... >= 512
            const int w = (tid >> 5) - 12;
            int t0 = (Tt - 1) - w;
            float4 f0 = __ldg(p4 + (size_t)t0 * 64 + lane);
            float4 f1 = __ldg(p4 + (size_t)t0 * 64 + lane + 32);
            float4 g0 = __ldg(p4 + (size_t)(t0 - 4) * 64 + lane);
            float4 g1 = __ldg(p4 + (size_t)(t0 - 4) * 64 + lane + 32);
            for (int t = t0; t >= TM; t -= 4) {
                int t2 = t - 8;
                float4 h0, h1;
                if (t2 >= TM) {
                    h0 = __ldg(p4 + (size_t)t2 * 64 + lane);
                    h1 = __ldg(p4 + (size_t)t2 * 64 + lane + 32);
                }
                if (t <= Tt - 1 - RSTG) { while (ld_acq_i(&s_tdB) - RSTG > t) { } }
                float4* dst = (float4*)ringB[t & (RSTG - 1)];
                dst[lane] = f0; dst[lane + 32] = f1;
                __syncwarp();
                float S = ex2f_(f0.x * INV_LN2) + ex2f_(f0.y * INV_LN2)
                        + ex2f_(f0.z * INV_LN2) + ex2f_(f0.w * INV_LN2)
                        + ex2f_(f1.x * INV_LN2) + ex2f_(f1.y * INV_LN2)
                        + ex2f_(f1.z * INV_LN2) + ex2f_(f1.w * INV_LN2);
#pragma unroll
                for (int o = 16; o; o >>= 1) S += __shfl_xor_sync(0xffffffffu, S, o);
                if (lane == 0) st_rel_f(&s_lse[t], lg2f_(S));
                f0 = g0; f1 = g1; g0 = h0; g1 = h1;
            }
        }
        return;
    }

    if (grp == 0) {
        // ======================= forward recursion =======================
        const int i = tid;                     // owns s = 2i, 2i+1 (+ s=256 on i==0)
        int myc = s_tg[i];
        int pv2 = (i >= 1) ? s_tg[i - 1] : 0;
        const bool sk = (myc != 0) && (myc != pv2);

        // t=0 init from ringF[0]
        float lse0 = ld_acq_f(&s_lse[0]);
        while (lse0 == MAGIC) lse0 = ld_acq_f(&s_lse[0]);
        {
            float rE = (i == 0) ? (ringF[0][0]       * INV_LN2 - lse0) : NEGV; // s=0
            float rO = (i == 0) ? (ringF[0][s_tg[0]] * INV_LN2 - lse0) : NEGV; // s=1
            ((float2*)&As[0][2])[i] = make_float2(rE, rO);
        }
        BARF();

        float lp2B, lp2L;
        {
            float l1 = ld_acq_f(&s_lse[1]);
            while (l1 == MAGIC) l1 = ld_acq_f(&s_lse[1]);
            lp2B = ringF[1][0]   * INV_LN2 - l1;
            lp2L = ringF[1][myc] * INV_LN2 - l1;
        }

        for (int t = 1; t < TM; ++t) {
            const int p = (t - 1) & 1, c = t & 1;
            const float2* src = (const float2*)&As[p][0];
            float2 v0 = src[i];        // s = 2i-2, 2i-1
            float2 v1 = src[i + 1];    // s = 2i,   2i+1
            float aEm1 = v0.y, aE0 = v1.x, aO0 = v1.y;

            float m  = fmaxf(fmaxf(aE0, aEm1), aO0);
            float e0 = ex2f_(aE0  - m);
            float e1 = ex2f_(aEm1 - m);
            float e2 = ex2f_(aO0  - m);
            float rE = fmaxf(m + lg2f_(e0 + e1) + lp2B, NEGV);
            float rO = fmaxf(m + lg2f_(e2 + e0 + (sk ? e1 : 0.0f)) + lp2L, NEGV);
            ((float2*)&As[c][2])[i] = make_float2(rE, rO);

            if (i == 0) {              // s=256 (blank): stay + step
                float a255 = As[p][257], a256 = As[p][258];
                float m2 = fmaxf(a255, a256);
                As[c][258] = fmaxf(m2 + lg2f_(ex2f_(a255 - m2) + ex2f_(a256 - m2)) + lp2B, NEGV);
            }
            BARF();
            if (tid == 0) st_rel_i(&s_tdF, t);

            int tn = (t + 1 < TM) ? (t + 1) : (TM - 1);
            float lse = ld_acq_f(&s_lse[tn]);
            while (lse == MAGIC) lse = ld_acq_f(&s_lse[tn]);
            lp2B = ringF[tn & (RSTG - 1)][0]   * INV_LN2 - lse;
            lp2L = ringF[tn & (RSTG - 1)][myc] * INV_LN2 - lse;
        }
        // alpha_{511} now in As[1] (511 & 1)

        BARC();   // wait for beta~_512 in Bs[0]

        // ---- combine: one emission-free transition step + logsumexp dot ----
        {
            const float2* src = (const float2*)&As[1][0];
            float2 v0 = src[i];
            float2 v1 = src[i + 1];
            float aEm1 = v0.y, aE0 = v1.x, aO0 = v1.y;
            float m  = fmaxf(fmaxf(aE0, aEm1), aO0);
            float e0 = ex2f_(aE0  - m);
            float e1 = ex2f_(aEm1 - m);
            float e2 = ex2f_(aO0  - m);
            float vE = m + lg2f_(e0 + e1)                         + Bs[0][2 * i];     // s'=2i
            float vO = m + lg2f_(e2 + e0 + (sk ? e1 : 0.0f))      + Bs[0][2 * i + 1]; // s'=2i+1

            float M = fmaxf(vE, vO);
            float E = ex2f_(vE - M) + ex2f_(vO - M);
            if (i == 0) {    // s'=256
                float a255 = As[1][257], a256 = As[1][258];
                float m2 = fmaxf(a255, a256);
                float v256 = m2 + lg2f_(ex2f_(a255 - m2) + ex2f_(a256 - m2)) + Bs[0][256];
                float nm = fmaxf(M, v256);
                E = E * ex2f_(M - nm) + ex2f_(v256 - nm);
                M = nm;
            }
#pragma unroll
            for (int o = 16; o; o >>= 1) {
                float om = __shfl_xor_sync(0xffffffffu, M, o);
                float oe = __shfl_xor_sync(0xffffffffu, E, o);
                float nm = fmaxf(M, om);
                E = E * ex2f_(M - nm) + oe * ex2f_(om - nm);
                M = nm;
            }
            if ((tid & 31) == 0) { red[2 * (tid >> 5)] = M; red[2 * (tid >> 5) + 1] = E; }
            BARF();
            if (tid == 0) {
                float Mf = red[0], Ef = red[1];
#pragma unroll
                for (int wv = 1; wv < 4; ++wv) {
                    float om = red[2 * wv], oe = red[2 * wv + 1];
                    float nm = fmaxf(Mf, om);
                    Ef = Ef * ex2f_(Mf - nm) + oe * ex2f_(om - nm);
                    Mf = nm;
                }
                float fin = (Mf + lg2f_(Ef)) * LN2;
                float loss = (fin < -1e29f) ? 0.0f : -fin;        // zero_infinity
                int tld = (tl > 0) ? tl : 1;
                g_losses[n] = loss / (float)tld;
            }
        }
        return;
    }

    // ======================= backward recursion =======================
    {
        const int j = tid - 128;               // owns s = 2j, 2j+1 (+ s=256 on j==0)
        int myc = s_tg[j];
        int nxt = (j + 1 < Ll) ? s_tg[j + 1] : 0;
        const bool skb = (nxt != 0) && (nxt != myc);

        // t = 1023 init: beta~(s) = lp(s) at s in {2tl, 2tl-1} (wrap tl==0 -> 256)
        float lseE = ld_acq_f(&s_lse[Tt - 1]);
        while (lseE == MAGIC) lseE = ld_acq_f(&s_lse[Tt - 1]);
        {
            const float* rw = ringB[(Tt - 1) & (RSTG - 1)];
            float lpB = rw[0]   * INV_LN2 - lseE;
            float lpL = rw[myc] * INV_LN2 - lseE;
            float rE = (2 * j == 2 * tl)     ? lpB : NEGV;     // even s = 2j
            float rO = (j == tl - 1)         ? lpL : NEGV;     // odd  s = 2j+1 == 2tl-1
            ((float2*)&Bs[1][0])[j] = make_float2(rE, rO);
            if (j == 0) Bs[1][256] = (tl == Ll || tl == 0) ? lpB : NEGV;  // s=256
        }
        BARB();

        float lp2B, lp2L;
        {
            float l1 = ld_acq_f(&s_lse[Tt - 2]);
            while (l1 == MAGIC) l1 = ld_acq_f(&s_lse[Tt - 2]);
            lp2B = ringB[(Tt - 2) & (RSTG - 1)][0]   * INV_LN2 - l1;
            lp2L = ringB[(Tt - 2) & (RSTG - 1)][myc] * INV_LN2 - l1;
        }

        for (int t = Tt - 2; t >= TM; --t) {
            const int p = (t + 1) & 1, c = t & 1;
            const float2* src = (const float2*)&Bs[p][0];
            float2 v1 = src[j];        // s = 2j,   2j+1
            float2 v0 = src[j + 1];    // s = 2j+2, 2j+3
            float bE0 = v1.x, bO0 = v1.y, bE1 = v0.x, bO1 = v0.y;

            float bS = skb ? bO1 : NEGV;
            float m  = fmaxf(fmaxf(bE0, bO0), fmaxf(bE1, bS));
            float e0 = ex2f_(bE0 - m);
            float e1 = ex2f_(bO0 - m);
            float e2 = ex2f_(bE1 - m);
            float e3 = skb ? ex2f_(bS - m) : 0.0f;
            float rE = fmaxf(m + lg2f_(e0 + e1)      + lp2B, NEGV);   // even: stay+step
            float rO = fmaxf(m + lg2f_(e1 + e2 + e3) + lp2L, NEGV);   // odd: stay+step+skip
            ((float2*)&Bs[c][0])[j] = make_float2(rE, rO);

            if (j == 0)                // s=256 top blank: self only
                Bs[c][256] = fmaxf(Bs[p][256] + lp2B, NEGV);

            BARB();
            if (tid == 128) st_rel_i(&s_tdB, t);

            int tn = (t - 1 >= TM) ? (t - 1) : TM;
            float lse = ld_acq_f(&s_lse[tn]);
            while (lse == MAGIC) lse = ld_acq_f(&s_lse[tn]);
            lp2B = ringB[tn & (RSTG - 1)][0]   * INV_LN2 - lse;
            lp2L = ringB[tn & (RSTG - 1)][myc] * INV_LN2 - lse;
        }
        // beta~_512 now in Bs[0] (512 & 1 = 0)
        BARC();
        return;
    }
}

// ---------------------------------------------------------------------------
__global__ void __launch_bounds__(128) reduce_kernel(float* __restrict__ out) {
    int tid = threadIdx.x;
    float v = g_losses[tid];
#pragma unroll
    for (int o = 16; o; o >>= 1) v += __shfl_xor_sync(0xffffffffu, v, o);
    __shared__ float sm[4];
    if ((tid & 31) == 0) sm[tid >> 5] = v;
    __syncthreads();
    if (tid == 0) out[0] = (sm[0] + sm[1] + sm[2] + sm[3]) * (1.0f / (float)Nn);
}

// ---------------------------------------------------------------------------
extern "C" void kernel_launch(void* const* d_in, const int* in_sizes, int n_in,
                              void* d_out, int out_size) {
    const float* preds;
    const int*   targets;
    if (in_sizes[0] == Nn * Tt * Cc) {
        preds   = (const float*)d_in[0];
        targets = (const int*)  d_in[1];
    } else {
        preds   = (const float*)d_in[1];
        targets = (const int*)  d_in[0];
    }
    float* out = (float*)d_out;

    ctc_fused   <<<Nn, 512>>>(preds, targets);
    reduce_kernel<<<1, 128>>>(out);
}